// round 6
// baseline (speedup 1.0000x reference)
#include <cuda_runtime.h>
#include <cuda_bf16.h>
#include <cstdint>

#define T_ 12
#define N_ 10000
#define E_ 160000
#define P_ 30000
#define DIN_ 128
#define H_ 64
#define NG 24            // 2*T graphs
#define M_ (NG * N_)     // 240000 rows
#define NE_ALL (NG * E_) // 3,840,000 edges
#define HB 8             // hist blocks per graph
#define EPB (E_ / HB)    // 20000 edges per hist block

typedef unsigned long long u64;

// Scratch (allocation-free rule: __device__ globals)
__device__ float g_xp[(size_t)M_ * 128];   // [row][0:64]=x@w_self, [64:128]=x@w_neigh
__device__ float g_acc[(size_t)M_ * 64];   // normalized h
__device__ int   g_deg[M_];
__device__ int   g_off[M_];                // CSR start (global, includes g*E_ base)
__device__ int   g_rank[NE_ALL];           // final slot rank of edge within its dst bucket
__device__ int   g_elist[NE_ALL];          // src node id per CSR slot

// ---------------------------------------------------------------------------
// packed fp32x2 helpers (Blackwell FFMA2 — 2x fma throughput, exact fp32)
// ---------------------------------------------------------------------------
__device__ __forceinline__ u64 pack_dup(float a) {
    u64 r; asm("mov.b64 %0, {%1, %1};" : "=l"(r) : "f"(a)); return r;
}
__device__ __forceinline__ void ffma2(u64& d, u64 a, u64 b) {
    asm("fma.rn.f32x2 %0, %1, %2, %0;" : "+l"(d) : "l"(a), "l"(b));
}
__device__ __forceinline__ float2 unpack2(u64 v) {
    float x, y; asm("mov.b64 {%0, %1}, %2;" : "=f"(x), "=f"(y) : "l"(v));
    return make_float2(x, y);
}

// ---------------------------------------------------------------------------
// Kernel 1: xp = x @ [w_self | w_neigh]  (R3 64-row tile, 2 CTAs/SM)
// ---------------------------------------------------------------------------
__global__ void gemm_proj(const float* __restrict__ x,
                          const float* __restrict__ w_self,
                          const float* __restrict__ w_neigh) {
    extern __shared__ float smem[];
    float* As = smem;              // [k=128][r=64]
    float* Bs = smem + 128 * 64;   // [k=128][c=128]
    const int tid = threadIdx.x;
    const int R0 = blockIdx.x * 64;

    {
        const int r = tid >> 2;
        const int kq = (tid & 3) * 32;
        const float4* xr = reinterpret_cast<const float4*>(
            x + (size_t)(R0 + r) * 128 + kq);
        #pragma unroll
        for (int i = 0; i < 8; i++) {
            float4 v = xr[i];
            int k = kq + i * 4;
            As[(k + 0) * 64 + r] = v.x;
            As[(k + 1) * 64 + r] = v.y;
            As[(k + 2) * 64 + r] = v.z;
            As[(k + 3) * 64 + r] = v.w;
        }
    }
    {
        #pragma unroll
        for (int i = 0; i < 16; i++) {
            int idx4 = tid + i * 256;
            int k = idx4 >> 5;
            int c = (idx4 & 31) * 4;
            float4 v;
            if (c < 64) v = *reinterpret_cast<const float4*>(w_self + k * 64 + c);
            else        v = *reinterpret_cast<const float4*>(w_neigh + k * 64 + (c - 64));
            *reinterpret_cast<float4*>(Bs + k * 128 + c) = v;
        }
    }
    __syncthreads();

    const int tx = tid & 15;      // 8 cols (4 f32x2 pairs)
    const int ty = tid >> 4;      // 4 rows
    u64 acc2[4][4];
    #pragma unroll
    for (int i = 0; i < 4; i++)
        #pragma unroll
        for (int j = 0; j < 4; j++) acc2[i][j] = 0ull;

    #pragma unroll 4
    for (int k = 0; k < 128; k++) {
        float4 a = *reinterpret_cast<const float4*>(As + k * 64 + ty * 4);
        longlong2 p0 = *reinterpret_cast<const longlong2*>(Bs + k * 128 + tx * 8);
        longlong2 p1 = *reinterpret_cast<const longlong2*>(Bs + k * 128 + tx * 8 + 4);
        u64 bv[4] = {(u64)p0.x, (u64)p0.y, (u64)p1.x, (u64)p1.y};
        u64 ad[4] = {pack_dup(a.x), pack_dup(a.y), pack_dup(a.z), pack_dup(a.w)};
        #pragma unroll
        for (int i = 0; i < 4; i++)
            #pragma unroll
            for (int j = 0; j < 4; j++)
                ffma2(acc2[i][j], ad[i], bv[j]);
    }

    #pragma unroll
    for (int i = 0; i < 4; i++) {
        size_t row = (size_t)(R0 + ty * 4 + i);
        float2 c0 = unpack2(acc2[i][0]);
        float2 c1 = unpack2(acc2[i][1]);
        float2 c2 = unpack2(acc2[i][2]);
        float2 c3 = unpack2(acc2[i][3]);
        float4 o0 = make_float4(c0.x, c0.y, c1.x, c1.y);
        float4 o1 = make_float4(c2.x, c2.y, c3.x, c3.y);
        *reinterpret_cast<float4*>(g_xp + row * 128 + tx * 8)     = o0;
        *reinterpret_cast<float4*>(g_xp + row * 128 + tx * 8 + 4) = o1;
    }
}

// ---------------------------------------------------------------------------
// CSR build: privatized-smem histogram producing per-edge final rank.
// grid = NG*HB (192) blocks of 512 threads; each handles EPB edges.
// ---------------------------------------------------------------------------
__global__ void hist_k(const int* __restrict__ dst) {
    __shared__ int sh[N_];                 // 40KB
    const int g = blockIdx.x / HB;
    const int chunk = blockIdx.x % HB;
    const int t = threadIdx.x;
    for (int b = t; b < N_; b += 512) sh[b] = 0;
    __syncthreads();

    const int base_e = g * E_ + chunk * EPB;
    for (int i = t; i < EPB; i += 512) {
        int e = base_e + i;
        g_rank[e] = atomicAdd(&sh[dst[e]], 1);   // local rank within block
    }
    __syncthreads();

    // flush counts; sh[b] becomes this block's base within node b's count
    for (int b = t; b < N_; b += 512) {
        int c = sh[b];
        sh[b] = (c > 0) ? atomicAdd(&g_deg[g * N_ + b], c) : 0;
    }
    __syncthreads();

    for (int i = t; i < EPB; i += 512) {
        int e = base_e + i;
        g_rank[e] += sh[dst[e]];                 // final rank in [0, deg)
    }
}

__global__ void scan_k() {
    const int g = blockIdx.x;
    const int t = threadIdx.x;           // 0..1023
    __shared__ int sm[1024];
    const int base = g * N_;
    int loc[10];
    int s = 0;
    if (t < 1000) {
        #pragma unroll
        for (int i = 0; i < 10; i++) {
            loc[i] = g_deg[base + t * 10 + i];
            s += loc[i];
        }
    }
    sm[t] = s;
    __syncthreads();
    #pragma unroll
    for (int off = 1; off < 1024; off <<= 1) {
        int v = (t >= off) ? sm[t - off] : 0;
        __syncthreads();
        sm[t] += v;
        __syncthreads();
    }
    if (t < 1000) {
        int run = (t > 0 ? sm[t - 1] : 0) + g * E_;
        #pragma unroll
        for (int i = 0; i < 10; i++) {
            g_off[base + t * 10 + i] = run;
            run += loc[i];
        }
    }
}

// fill without atomics: pos = g_off[node] + rank[e]
__global__ void fill_k(const int4* __restrict__ src4,
                       const int4* __restrict__ dst4) {
    int t = blockIdx.x * blockDim.x + threadIdx.x;
    if (t >= NE_ALL / 4) return;
    int g = (t * 4) / E_;                   // E_ % 4 == 0
    int4 d = dst4[t];
    int4 s = src4[t];
    int4 r = reinterpret_cast<const int4*>(g_rank)[t];
    int b = g * N_;
    g_elist[g_off[b + d.x] + r.x] = s.x;
    g_elist[g_off[b + d.y] + r.y] = s.y;
    g_elist[g_off[b + d.z] + r.z] = s.z;
    g_elist[g_off[b + d.w] + r.w] = s.w;
}

// ---------------------------------------------------------------------------
// Gather + finalize fused: warp per node, lane -> channels {2l, 2l+1}.
// ---------------------------------------------------------------------------
__global__ void gather_fin_k(const float* __restrict__ b_sage) {
    int node = (int)(((long)blockIdx.x * blockDim.x + threadIdx.x) >> 5);
    int lane = threadIdx.x & 31;
    if (node >= M_) return;
    int g = node / N_;
    int off = g_off[node];
    int deg = g_deg[node];
    const float* xpn = g_xp + 64 + lane * 2;   // neigh half
    size_t gbase = (size_t)g * N_;

    float sx = 0.f, sy = 0.f;
    int i = 0;
    for (; i + 4 <= deg; i += 4) {
        int s0 = g_elist[off + i + 0];
        int s1 = g_elist[off + i + 1];
        int s2 = g_elist[off + i + 2];
        int s3 = g_elist[off + i + 3];
        float2 v0 = *reinterpret_cast<const float2*>(xpn + (gbase + s0) * 128);
        float2 v1 = *reinterpret_cast<const float2*>(xpn + (gbase + s1) * 128);
        float2 v2 = *reinterpret_cast<const float2*>(xpn + (gbase + s2) * 128);
        float2 v3 = *reinterpret_cast<const float2*>(xpn + (gbase + s3) * 128);
        sx += (v0.x + v1.x) + (v2.x + v3.x);
        sy += (v0.y + v1.y) + (v2.y + v3.y);
    }
    for (; i < deg; i++) {
        int s0 = g_elist[off + i];
        float2 v0 = *reinterpret_cast<const float2*>(xpn + (gbase + s0) * 128);
        sx += v0.x;
        sy += v0.y;
    }

    float inv = 1.f / fmaxf((float)deg, 1.f);
    float2 self = *reinterpret_cast<const float2*>(
        g_xp + (size_t)node * 128 + lane * 2);
    float2 bs = *reinterpret_cast<const float2*>(b_sage + lane * 2);
    float h0 = self.x + sx * inv + bs.x;
    float h1 = self.y + sy * inv + bs.y;
    float ss = h0 * h0 + h1 * h1;
    #pragma unroll
    for (int o = 16; o > 0; o >>= 1)
        ss += __shfl_xor_sync(0xFFFFFFFFu, ss, o);
    float sc = 1.f / fmaxf(sqrtf(ss), 1e-12f);
    float2 outv = make_float2(h0 * sc, h1 * sc);
    *reinterpret_cast<float2*>(g_acc + (size_t)node * 64 + lane * 2) = outv;
}

// ---------------------------------------------------------------------------
// Attention: warp per pair.
// ---------------------------------------------------------------------------
__device__ __forceinline__ float fsigmoid(float x) {
    float t;
    asm("tanh.approx.f32 %0, %1;" : "=f"(t) : "f"(0.5f * x));
    return fmaf(0.5f, t, 0.5f);
}

__global__ void attn_k(const int* __restrict__ idx,
                       const float* __restrict__ w_ff2,
                       const float* __restrict__ b_ff2,
                       const float* __restrict__ w_ff1,
                       const float* __restrict__ b_ff1,
                       const float* __restrict__ w_out,
                       float* __restrict__ out) {
    int p = (int)(((long)blockIdx.x * blockDim.x + threadIdx.x) >> 5);
    int lane = threadIdx.x & 31;
    if (p >= P_) return;
    const int cb = lane * 4;

    float w2[4], wo[4];
    #pragma unroll
    for (int j = 0; j < 4; j++) { w2[j] = w_ff2[cb + j]; wo[j] = w_out[cb + j]; }
    const float bf2 = *b_ff2;
    const float bf1 = *b_ff1;

    float tv[T_][4];
    #pragma unroll
    for (int t = 0; t < T_; t++) {
        int i0 = idx[t * P_ + p];
        int i1 = idx[T_ * P_ + t * P_ + p];
        const float* row = (lane < 16)
            ? g_acc + ((size_t)(t * N_ + i0)) * 64 + cb
            : g_acc + ((size_t)((T_ + t) * N_ + i1)) * 64 + (cb - 64);
        float4 v = *reinterpret_cast<const float4*>(row);
        tv[t][0] = v.x; tv[t][1] = v.y; tv[t][2] = v.z; tv[t][3] = v.w;
    }

    float u[T_];
    #pragma unroll
    for (int t = 0; t < T_; t++) {
        float s = tv[t][0] * w2[0];
        s = fmaf(tv[t][1], w2[1], s);
        s = fmaf(tv[t][2], w2[2], s);
        s = fmaf(tv[t][3], w2[3], s);
        u[t] = s;
    }
    #pragma unroll
    for (int off = 16; off > 0; off >>= 1)
        #pragma unroll
        for (int t = 0; t < T_; t++)
            u[t] += __shfl_xor_sync(0xFFFFFFFFu, u[t], off);

    float s0 = 0.f, s1 = 0.f, s2 = 0.f;
    #pragma unroll
    for (int t = 0; t < T_; t++) {
        float wf = w_ff1[t];
        float d0 = u[t] - (t > 0 ? u[t - 1] : 0.f);
        float d1 = u[t] - (t > 1 ? u[t - 2] : 0.f);
        float d2 = u[t] - (t > 2 ? u[t - 3] : 0.f);
        s0 = fmaf(fmaxf(d0 + bf2, 0.f), wf, s0);
        s1 = fmaf(fmaxf(d1 + bf2, 0.f), wf, s1);
        s2 = fmaf(fmaxf(d2 + bf2, 0.f), wf, s2);
    }
    s0 += bf1; s1 += bf1; s2 += bf1;
    float mx = fmaxf(s0, fmaxf(s1, s2));
    float e0 = __expf(s0 - mx), e1 = __expf(s1 - mx), e2 = __expf(s2 - mx);
    float inv = 1.f / (e0 + e1 + e2);
    float sw[3] = {e0 * inv, e1 * inv, e2 * inv};

    float o[T_];
    #pragma unroll
    for (int t = 0; t < T_; t++) {
        float acc = 0.f;
        #pragma unroll
        for (int j = 0; j < 4; j++) {
            float att = 0.f;
            #pragma unroll
            for (int km = 0; km < 3; km++) {
                float d = tv[t][j] - (t > km ? tv[t - km - 1][j] : 0.f);
                att = fmaf(sw[km], fsigmoid(d), att);
            }
            acc = fmaf(tv[t][j] * att, wo[j], acc);
        }
        o[t] = acc;
    }
    #pragma unroll
    for (int off = 16; off > 0; off >>= 1)
        #pragma unroll
        for (int t = 0; t < T_; t++)
            o[t] += __shfl_xor_sync(0xFFFFFFFFu, o[t], off);

    if (lane == 0) {
        #pragma unroll
        for (int t = 0; t < T_; t++)
            out[t * P_ + p] = o[t];
    }
}

// ---------------------------------------------------------------------------
extern "C" void kernel_launch(void* const* d_in, const int* in_sizes, int n_in,
                              void* d_out, int out_size) {
    const float* x       = (const float*)d_in[0];
    const int*   src     = (const int*)  d_in[1];
    const int*   dst     = (const int*)  d_in[2];
    const int*   idx     = (const int*)  d_in[3];
    const float* w_self  = (const float*)d_in[4];
    const float* w_neigh = (const float*)d_in[5];
    const float* b_sage  = (const float*)d_in[6];
    const float* w_ff2   = (const float*)d_in[7];
    const float* b_ff2   = (const float*)d_in[8];
    const float* w_ff1   = (const float*)d_in[9];
    const float* b_ff1   = (const float*)d_in[10];
    const float* w_out   = (const float*)d_in[11];
    float* out = (float*)d_out;

    // One-time stream/event creation (host objects, no device memory).
    static cudaStream_t s2 = nullptr;
    static cudaEvent_t evFork = nullptr, evJoin = nullptr;
    if (!s2) {
        cudaStreamCreate(&s2);
        cudaEventCreateWithFlags(&evFork, cudaEventDisableTiming);
        cudaEventCreateWithFlags(&evJoin, cudaEventDisableTiming);
    }

    void* degPtr = nullptr; cudaGetSymbolAddress(&degPtr, g_deg);
    cudaMemsetAsync(degPtr, 0, (size_t)M_ * sizeof(int));

    const size_t smem = (128 * 64 + 128 * 128) * sizeof(float);  // 96KB
    cudaFuncSetAttribute(gemm_proj, cudaFuncAttributeMaxDynamicSharedMemorySize,
                         (int)smem);

    // Fork: CSR build chain on s2 (independent of GEMM)
    cudaEventRecord(evFork, 0);
    cudaStreamWaitEvent(s2, evFork, 0);

    hist_k<<<NG * HB, 512, 0, s2>>>(dst);
    scan_k<<<NG, 1024, 0, s2>>>();
    int e4blocks = (NE_ALL / 4 + 255) / 256;
    fill_k<<<e4blocks, 256, 0, s2>>>((const int4*)src, (const int4*)dst);
    cudaEventRecord(evJoin, s2);

    // GEMM on the main stream, concurrent with the CSR chain
    gemm_proj<<<M_ / 64, 256, smem>>>(x, w_self, w_neigh);

    // Join: gather needs both g_xp (gemm) and g_elist/g_off/g_deg (CSR)
    cudaStreamWaitEvent(0, evJoin, 0);

    gather_fin_k<<<(M_ * 32 + 255) / 256, 256>>>(b_sage);

    attn_k<<<(P_ * 32 + 255) / 256, 256>>>(idx, w_ff2, b_ff2, w_ff1, b_ff1,
                                           w_out, out);
}

// round 8
// speedup vs baseline: 1.2048x; 1.2048x over previous
#include <cuda_runtime.h>
#include <cuda_bf16.h>
#include <cstdint>

#define T_ 12
#define N_ 10000
#define E_ 160000
#define P_ 30000
#define DIN_ 128
#define H_ 64
#define NG 24            // 2*T graphs
#define M_ (NG * N_)     // 240000 rows
#define NE_ALL (NG * E_) // 3,840,000 edges
#define HB 8             // hist blocks per graph
#define EPB (E_ / HB)    // 20000 edges per hist block

typedef unsigned long long u64;

// Scratch (allocation-free rule: __device__ globals)
__device__ float g_xp[(size_t)M_ * 128];   // xp = x @ [w_self | w_neigh]
__device__ float g_acc[(size_t)M_ * 64];   // normalized h
__device__ int   g_deg[M_];
__device__ int   g_off[M_];                // CSR start (global, includes g*E_ base)
__device__ int   g_rank[NE_ALL];           // final slot rank of edge within its dst bucket
__device__ int   g_elist[NE_ALL];          // src node id per CSR slot
__device__ uint32_t g_Bt[128 * 128];       // B^T as [n][k], tf32-rounded bits

__device__ __forceinline__ uint32_t tf32_rna(float f) {
    uint32_t u;
    asm("cvt.rna.tf32.f32 %0, %1;" : "=r"(u) : "f"(f));
    return u;
}

// ---------------------------------------------------------------------------
// B prep: g_Bt[n][k] = tf32(W[k][n]);  n<64 -> w_self col n, else w_neigh col n-64
// ---------------------------------------------------------------------------
__global__ void b_prep(const float* __restrict__ w_self,
                       const float* __restrict__ w_neigh) {
    int idx = blockIdx.x * blockDim.x + threadIdx.x;   // 0..16383
    int n = idx >> 7;
    int k = idx & 127;
    const float* wsrc = (n < 64) ? (w_self + n) : (w_neigh + (n - 64));
    g_Bt[n * 128 + k] = tf32_rna(wsrc[k * 64]);
}

// ---------------------------------------------------------------------------
// tf32 mma.sync GEMM: 128x128 tile per CTA, 8 warps, warp tile 32x64.
// ---------------------------------------------------------------------------
#define SSTR 132   // padded row stride (words)

__global__ __launch_bounds__(256, 1)
void gemm_mma(const float* __restrict__ x) {
    extern __shared__ uint32_t smem[];
    uint32_t* As = smem;               // [128][SSTR] tf32 bits of x tile (row r, col k)
    uint32_t* Bs = smem + 128 * SSTR;  // [128][SSTR] tf32 bits of B^T (row n, col k)
    const int tid = threadIdx.x;
    const int wid = tid >> 5;
    const int lane = tid & 31;
    const int R0 = blockIdx.x * 128;

    // stage A (tf32-rounded) and B
    {
        const float4* x4 = reinterpret_cast<const float4*>(x) + (size_t)R0 * 32;
        const uint4* b4 = reinterpret_cast<const uint4*>(g_Bt);
        #pragma unroll
        for (int i = 0; i < 16; i++) {
            int idx = tid + i * 256;     // 4096 chunks
            int r = idx >> 5;
            int c4 = idx & 31;
            float4 v = x4[idx];
            uint4 u;
            u.x = tf32_rna(v.x); u.y = tf32_rna(v.y);
            u.z = tf32_rna(v.z); u.w = tf32_rna(v.w);
            *reinterpret_cast<uint4*>(As + r * SSTR + c4 * 4) = u;
            *reinterpret_cast<uint4*>(Bs + r * SSTR + c4 * 4) = b4[idx];
        }
    }
    __syncthreads();

    const int wrow = (wid & 3) * 32;    // warp row base within tile
    const int wcol = (wid >> 2) * 64;   // warp col base within tile
    const int lq = lane >> 2;           // 0..7
    const int lr = lane & 3;            // 0..3

    float acc[2][8][4];
    #pragma unroll
    for (int m = 0; m < 2; m++)
        #pragma unroll
        for (int n = 0; n < 8; n++)
            #pragma unroll
            for (int j = 0; j < 4; j++) acc[m][n][j] = 0.f;

    #pragma unroll
    for (int ks = 0; ks < 16; ks++) {
        const int kc = ks * 8 + lr;
        uint32_t a[2][4];
        #pragma unroll
        for (int m = 0; m < 2; m++) {
            int rbase = wrow + m * 16 + lq;
            a[m][0] = As[rbase * SSTR + kc];
            a[m][1] = As[(rbase + 8) * SSTR + kc];
            a[m][2] = As[rbase * SSTR + kc + 4];
            a[m][3] = As[(rbase + 8) * SSTR + kc + 4];
        }
        uint32_t b[8][2];
        #pragma unroll
        for (int n = 0; n < 8; n++) {
            int nrow = wcol + n * 8 + lq;
            b[n][0] = Bs[nrow * SSTR + kc];
            b[n][1] = Bs[nrow * SSTR + kc + 4];
        }
        #pragma unroll
        for (int m = 0; m < 2; m++)
            #pragma unroll
            for (int n = 0; n < 8; n++) {
                asm volatile(
                    "mma.sync.aligned.m16n8k8.row.col.f32.tf32.tf32.f32 "
                    "{%0,%1,%2,%3}, {%4,%5,%6,%7}, {%8,%9}, {%0,%1,%2,%3};"
                    : "+f"(acc[m][n][0]), "+f"(acc[m][n][1]),
                      "+f"(acc[m][n][2]), "+f"(acc[m][n][3])
                    : "r"(a[m][0]), "r"(a[m][1]), "r"(a[m][2]), "r"(a[m][3]),
                      "r"(b[n][0]), "r"(b[n][1]));
            }
    }

    // epilogue: c0,c1 -> (row, col..col+1); c2,c3 -> (row+8, col..col+1)
    #pragma unroll
    for (int m = 0; m < 2; m++) {
        size_t row = (size_t)(R0 + wrow + m * 16 + lq);
        #pragma unroll
        for (int n = 0; n < 8; n++) {
            int col = wcol + n * 8 + 2 * lr;
            *reinterpret_cast<float2*>(g_xp + row * 128 + col) =
                make_float2(acc[m][n][0], acc[m][n][1]);
            *reinterpret_cast<float2*>(g_xp + (row + 8) * 128 + col) =
                make_float2(acc[m][n][2], acc[m][n][3]);
        }
    }
}

// ---------------------------------------------------------------------------
// CSR build: privatized-smem histogram producing per-edge final rank.
// ---------------------------------------------------------------------------
__global__ void hist_k(const int* __restrict__ dst) {
    __shared__ int sh[N_];                 // 40KB
    const int g = blockIdx.x / HB;
    const int chunk = blockIdx.x % HB;
    const int t = threadIdx.x;
    for (int b = t; b < N_; b += 512) sh[b] = 0;
    __syncthreads();

    const int base_e = g * E_ + chunk * EPB;
    for (int i = t; i < EPB; i += 512) {
        int e = base_e + i;
        g_rank[e] = atomicAdd(&sh[dst[e]], 1);
    }
    __syncthreads();

    for (int b = t; b < N_; b += 512) {
        int c = sh[b];
        sh[b] = (c > 0) ? atomicAdd(&g_deg[g * N_ + b], c) : 0;
    }
    __syncthreads();

    for (int i = t; i < EPB; i += 512) {
        int e = base_e + i;
        g_rank[e] += sh[dst[e]];
    }
}

__global__ void scan_k() {
    const int g = blockIdx.x;
    const int t = threadIdx.x;           // 0..1023
    __shared__ int sm[1024];
    const int base = g * N_;
    int loc[10];
    int s = 0;
    if (t < 1000) {
        #pragma unroll
        for (int i = 0; i < 10; i++) {
            loc[i] = g_deg[base + t * 10 + i];
            s += loc[i];
        }
    }
    sm[t] = s;
    __syncthreads();
    #pragma unroll
    for (int off = 1; off < 1024; off <<= 1) {
        int v = (t >= off) ? sm[t - off] : 0;
        __syncthreads();
        sm[t] += v;
        __syncthreads();
    }
    if (t < 1000) {
        int run = (t > 0 ? sm[t - 1] : 0) + g * E_;
        #pragma unroll
        for (int i = 0; i < 10; i++) {
            g_off[base + t * 10 + i] = run;
            run += loc[i];
        }
    }
}

__global__ void fill_k(const int4* __restrict__ src4,
                       const int4* __restrict__ dst4) {
    int t = blockIdx.x * blockDim.x + threadIdx.x;
    if (t >= NE_ALL / 4) return;
    int g = (t * 4) / E_;                   // E_ % 4 == 0
    int4 d = dst4[t];
    int4 s = src4[t];
    int4 r = reinterpret_cast<const int4*>(g_rank)[t];
    int b = g * N_;
    g_elist[g_off[b + d.x] + r.x] = s.x;
    g_elist[g_off[b + d.y] + r.y] = s.y;
    g_elist[g_off[b + d.z] + r.z] = s.z;
    g_elist[g_off[b + d.w] + r.w] = s.w;
}

// ---------------------------------------------------------------------------
// Gather + finalize fused: warp per node, lane -> channels {2l, 2l+1}.
// ---------------------------------------------------------------------------
__global__ void gather_fin_k(const float* __restrict__ b_sage) {
    int node = (int)(((long)blockIdx.x * blockDim.x + threadIdx.x) >> 5);
    int lane = threadIdx.x & 31;
    if (node >= M_) return;
    int g = node / N_;
    int off = g_off[node];
    int deg = g_deg[node];
    const float* xpn = g_xp + 64 + lane * 2;   // neigh half
    size_t gbase = (size_t)g * N_;

    float sx = 0.f, sy = 0.f;
    int i = 0;
    for (; i + 4 <= deg; i += 4) {
        int s0 = g_elist[off + i + 0];
        int s1 = g_elist[off + i + 1];
        int s2 = g_elist[off + i + 2];
        int s3 = g_elist[off + i + 3];
        float2 v0 = *reinterpret_cast<const float2*>(xpn + (gbase + s0) * 128);
        float2 v1 = *reinterpret_cast<const float2*>(xpn + (gbase + s1) * 128);
        float2 v2 = *reinterpret_cast<const float2*>(xpn + (gbase + s2) * 128);
        float2 v3 = *reinterpret_cast<const float2*>(xpn + (gbase + s3) * 128);
        sx += (v0.x + v1.x) + (v2.x + v3.x);
        sy += (v0.y + v1.y) + (v2.y + v3.y);
    }
    for (; i < deg; i++) {
        int s0 = g_elist[off + i];
        float2 v0 = *reinterpret_cast<const float2*>(xpn + (gbase + s0) * 128);
        sx += v0.x;
        sy += v0.y;
    }

    float inv = 1.f / fmaxf((float)deg, 1.f);
    float2 self = *reinterpret_cast<const float2*>(
        g_xp + (size_t)node * 128 + lane * 2);
    float2 bs = *reinterpret_cast<const float2*>(b_sage + lane * 2);
    float h0 = self.x + sx * inv + bs.x;
    float h1 = self.y + sy * inv + bs.y;
    float ss = h0 * h0 + h1 * h1;
    #pragma unroll
    for (int o = 16; o > 0; o >>= 1)
        ss += __shfl_xor_sync(0xFFFFFFFFu, ss, o);
    float sc = 1.f / fmaxf(sqrtf(ss), 1e-12f);
    float2 outv = make_float2(h0 * sc, h1 * sc);
    *reinterpret_cast<float2*>(g_acc + (size_t)node * 64 + lane * 2) = outv;
}

// ---------------------------------------------------------------------------
// Attention: warp per pair.
// ---------------------------------------------------------------------------
__device__ __forceinline__ float fsigmoid(float x) {
    float t;
    asm("tanh.approx.f32 %0, %1;" : "=f"(t) : "f"(0.5f * x));
    return fmaf(0.5f, t, 0.5f);
}

__global__ void attn_k(const int* __restrict__ idx,
                       const float* __restrict__ w_ff2,
                       const float* __restrict__ b_ff2,
                       const float* __restrict__ w_ff1,
                       const float* __restrict__ b_ff1,
                       const float* __restrict__ w_out,
                       float* __restrict__ out) {
    int p = (int)(((long)blockIdx.x * blockDim.x + threadIdx.x) >> 5);
    int lane = threadIdx.x & 31;
    if (p >= P_) return;
    const int cb = lane * 4;

    float w2[4], wo[4];
    #pragma unroll
    for (int j = 0; j < 4; j++) { w2[j] = w_ff2[cb + j]; wo[j] = w_out[cb + j]; }
    const float bf2 = *b_ff2;
    const float bf1 = *b_ff1;

    float tv[T_][4];
    #pragma unroll
    for (int t = 0; t < T_; t++) {
        int i0 = idx[t * P_ + p];
        int i1 = idx[T_ * P_ + t * P_ + p];
        const float* row = (lane < 16)
            ? g_acc + ((size_t)(t * N_ + i0)) * 64 + cb
            : g_acc + ((size_t)((T_ + t) * N_ + i1)) * 64 + (cb - 64);
        float4 v = *reinterpret_cast<const float4*>(row);
        tv[t][0] = v.x; tv[t][1] = v.y; tv[t][2] = v.z; tv[t][3] = v.w;
    }

    float u[T_];
    #pragma unroll
    for (int t = 0; t < T_; t++) {
        float s = tv[t][0] * w2[0];
        s = fmaf(tv[t][1], w2[1], s);
        s = fmaf(tv[t][2], w2[2], s);
        s = fmaf(tv[t][3], w2[3], s);
        u[t] = s;
    }
    #pragma unroll
    for (int off = 16; off > 0; off >>= 1)
        #pragma unroll
        for (int t = 0; t < T_; t++)
            u[t] += __shfl_xor_sync(0xFFFFFFFFu, u[t], off);

    float s0 = 0.f, s1 = 0.f, s2 = 0.f;
    #pragma unroll
    for (int t = 0; t < T_; t++) {
        float wf = w_ff1[t];
        float d0 = u[t] - (t > 0 ? u[t - 1] : 0.f);
        float d1 = u[t] - (t > 1 ? u[t - 2] : 0.f);
        float d2 = u[t] - (t > 2 ? u[t - 3] : 0.f);
        s0 = fmaf(fmaxf(d0 + bf2, 0.f), wf, s0);
        s1 = fmaf(fmaxf(d1 + bf2, 0.f), wf, s1);
        s2 = fmaf(fmaxf(d2 + bf2, 0.f), wf, s2);
    }
    s0 += bf1; s1 += bf1; s2 += bf1;
    float mx = fmaxf(s0, fmaxf(s1, s2));
    float e0 = __expf(s0 - mx), e1 = __expf(s1 - mx), e2 = __expf(s2 - mx);
    float inv = 1.f / (e0 + e1 + e2);
    float sw[3] = {e0 * inv, e1 * inv, e2 * inv};

    float o[T_];
    #pragma unroll
    for (int t = 0; t < T_; t++) {
        float acc = 0.f;
        #pragma unroll
        for (int j = 0; j < 4; j++) {
            float att = 0.f;
            #pragma unroll
            for (int km = 0; km < 3; km++) {
                float d = tv[t][j] - (t > km ? tv[t - km - 1][j] : 0.f);
                att = fmaf(sw[km], fsigmoid(d), att);
            }
            acc = fmaf(tv[t][j] * att, wo[j], acc);
        }
        o[t] = acc;
    }
    #pragma unroll
    for (int off = 16; off > 0; off >>= 1)
        #pragma unroll
        for (int t = 0; t < T_; t++)
            o[t] += __shfl_xor_sync(0xFFFFFFFFu, o[t], off);

    if (lane == 0) {
        #pragma unroll
        for (int t = 0; t < T_; t++)
            out[t * P_ + p] = o[t];
    }
}

// ---------------------------------------------------------------------------
extern "C" void kernel_launch(void* const* d_in, const int* in_sizes, int n_in,
                              void* d_out, int out_size) {
    const float* x       = (const float*)d_in[0];
    const int*   src     = (const int*)  d_in[1];
    const int*   dst     = (const int*)  d_in[2];
    const int*   idx     = (const int*)  d_in[3];
    const float* w_self  = (const float*)d_in[4];
    const float* w_neigh = (const float*)d_in[5];
    const float* b_sage  = (const float*)d_in[6];
    const float* w_ff2   = (const float*)d_in[7];
    const float* b_ff2   = (const float*)d_in[8];
    const float* w_ff1   = (const float*)d_in[9];
    const float* b_ff1   = (const float*)d_in[10];
    const float* w_out   = (const float*)d_in[11];
    float* out = (float*)d_out;

    static cudaStream_t s2 = nullptr;
    static cudaEvent_t evFork = nullptr, evJoin = nullptr;
    if (!s2) {
        cudaStreamCreate(&s2);
        cudaEventCreateWithFlags(&evFork, cudaEventDisableTiming);
        cudaEventCreateWithFlags(&evJoin, cudaEventDisableTiming);
        cudaFuncSetAttribute(gemm_mma, cudaFuncAttributeMaxDynamicSharedMemorySize,
                             2 * 128 * SSTR * 4);
    }

    void* degPtr = nullptr; cudaGetSymbolAddress(&degPtr, g_deg);
    cudaMemsetAsync(degPtr, 0, (size_t)M_ * sizeof(int));

    // Fork: CSR build chain on s2 (independent of GEMM)
    cudaEventRecord(evFork, 0);
    cudaStreamWaitEvent(s2, evFork, 0);

    hist_k<<<NG * HB, 512, 0, s2>>>(dst);
    scan_k<<<NG, 1024, 0, s2>>>();
    int e4blocks = (NE_ALL / 4 + 255) / 256;
    fill_k<<<e4blocks, 256, 0, s2>>>((const int4*)src, (const int4*)dst);
    cudaEventRecord(evJoin, s2);

    // GEMM path on main stream, concurrent with the CSR chain
    b_prep<<<64, 256>>>(w_self, w_neigh);
    gemm_mma<<<M_ / 128, 256, 2 * 128 * SSTR * 4>>>(x);

    cudaStreamWaitEvent(0, evJoin, 0);

    gather_fin_k<<<(M_ * 32 + 255) / 256, 256>>>(b_sage);

    attn_k<<<(P_ * 32 + 255) / 256, 256>>>(idx, w_ff2, b_ff2, w_ff1, b_ff1,
                                           w_out, out);
}

// round 9
// speedup vs baseline: 1.7207x; 1.4283x over previous
#include <cuda_runtime.h>
#include <cuda_bf16.h>
#include <cstdint>

#define T_ 12
#define N_ 10000
#define E_ 160000
#define P_ 30000
#define DIN_ 128
#define H_ 64
#define NG 24            // 2*T graphs
#define M_ (NG * N_)     // 240000 rows
#define NE_ALL (NG * E_) // 3,840,000 edges
#define HB 8             // hist blocks per graph
#define EPB (E_ / HB)    // 20000 edges per hist block

#define NTILES (M_ / 128)     // 1875
#define TILES_A 938           // rows 0..120063  (covers graphs 0..11 + 64 rows of g12)
#define TILES_B (NTILES - TILES_A)
#define NODES_HALF 120000     // graphs 0..11

typedef unsigned long long u64;

// Scratch (allocation-free rule: __device__ globals)
__device__ float g_xp[(size_t)M_ * 128];   // xp = x @ [w_self | w_neigh]
__device__ float g_acc[(size_t)M_ * 64];   // normalized h
__device__ int   g_deg[M_];
__device__ int   g_off[M_];                // CSR start (global, includes g*E_ base)
__device__ int   g_rank[NE_ALL];           // final slot rank of edge within its dst bucket
__device__ int   g_elist[NE_ALL];          // src node id per CSR slot
__device__ uint32_t g_Bt[128 * 128];       // B^T as [n][k], tf32-rounded bits

__device__ __forceinline__ uint32_t tf32_rna(float f) {
    uint32_t u;
    asm("cvt.rna.tf32.f32 %0, %1;" : "=r"(u) : "f"(f));
    return u;
}

// ---------------------------------------------------------------------------
// B prep: g_Bt[n][k] = tf32(W[k][n]);  n<64 -> w_self col n, else w_neigh col n-64
// ---------------------------------------------------------------------------
__global__ void b_prep(const float* __restrict__ w_self,
                       const float* __restrict__ w_neigh) {
    int idx = blockIdx.x * blockDim.x + threadIdx.x;   // 0..16383
    int n = idx >> 7;
    int k = idx & 127;
    const float* wsrc = (n < 64) ? (w_self + n) : (w_neigh + (n - 64));
    g_Bt[n * 128 + k] = tf32_rna(wsrc[k * 64]);
}

// ---------------------------------------------------------------------------
// tf32 mma.sync GEMM: 128x128 tile per CTA, 8 warps, warp tile 32x64.
// tile0 = starting tile index (split launches).
// ---------------------------------------------------------------------------
#define SSTR 132   // padded row stride (words)

__global__ __launch_bounds__(256, 1)
void gemm_mma(const float* __restrict__ x, int tile0) {
    extern __shared__ uint32_t smem[];
    uint32_t* As = smem;               // [128][SSTR] tf32 bits of x tile (row r, col k)
    uint32_t* Bs = smem + 128 * SSTR;  // [128][SSTR] tf32 bits of B^T (row n, col k)
    const int tid = threadIdx.x;
    const int wid = tid >> 5;
    const int lane = tid & 31;
    const int R0 = (tile0 + blockIdx.x) * 128;

    // stage A (tf32-rounded) and B
    {
        const float4* x4 = reinterpret_cast<const float4*>(x) + (size_t)R0 * 32;
        const uint4* b4 = reinterpret_cast<const uint4*>(g_Bt);
        #pragma unroll
        for (int i = 0; i < 16; i++) {
            int idx = tid + i * 256;     // 4096 chunks
            int r = idx >> 5;
            int c4 = idx & 31;
            float4 v = x4[idx];
            uint4 u;
            u.x = tf32_rna(v.x); u.y = tf32_rna(v.y);
            u.z = tf32_rna(v.z); u.w = tf32_rna(v.w);
            *reinterpret_cast<uint4*>(As + r * SSTR + c4 * 4) = u;
            *reinterpret_cast<uint4*>(Bs + r * SSTR + c4 * 4) = b4[idx];
        }
    }
    __syncthreads();

    const int wrow = (wid & 3) * 32;    // warp row base within tile
    const int wcol = (wid >> 2) * 64;   // warp col base within tile
    const int lq = lane >> 2;           // 0..7
    const int lr = lane & 3;            // 0..3

    float acc[2][8][4];
    #pragma unroll
    for (int m = 0; m < 2; m++)
        #pragma unroll
        for (int n = 0; n < 8; n++)
            #pragma unroll
            for (int j = 0; j < 4; j++) acc[m][n][j] = 0.f;

    #pragma unroll
    for (int ks = 0; ks < 16; ks++) {
        const int kc = ks * 8 + lr;
        uint32_t a[2][4];
        #pragma unroll
        for (int m = 0; m < 2; m++) {
            int rbase = wrow + m * 16 + lq;
            a[m][0] = As[rbase * SSTR + kc];
            a[m][1] = As[(rbase + 8) * SSTR + kc];
            a[m][2] = As[rbase * SSTR + kc + 4];
            a[m][3] = As[(rbase + 8) * SSTR + kc + 4];
        }
        uint32_t b[8][2];
        #pragma unroll
        for (int n = 0; n < 8; n++) {
            int nrow = wcol + n * 8 + lq;
            b[n][0] = Bs[nrow * SSTR + kc];
            b[n][1] = Bs[nrow * SSTR + kc + 4];
        }
        #pragma unroll
        for (int m = 0; m < 2; m++)
            #pragma unroll
            for (int n = 0; n < 8; n++) {
                asm volatile(
                    "mma.sync.aligned.m16n8k8.row.col.f32.tf32.tf32.f32 "
                    "{%0,%1,%2,%3}, {%4,%5,%6,%7}, {%8,%9}, {%0,%1,%2,%3};"
                    : "+f"(acc[m][n][0]), "+f"(acc[m][n][1]),
                      "+f"(acc[m][n][2]), "+f"(acc[m][n][3])
                    : "r"(a[m][0]), "r"(a[m][1]), "r"(a[m][2]), "r"(a[m][3]),
                      "r"(b[n][0]), "r"(b[n][1]));
            }
    }

    // epilogue: c0,c1 -> (row, col..col+1); c2,c3 -> (row+8, col..col+1)
    #pragma unroll
    for (int m = 0; m < 2; m++) {
        size_t row = (size_t)(R0 + wrow + m * 16 + lq);
        #pragma unroll
        for (int n = 0; n < 8; n++) {
            int col = wcol + n * 8 + 2 * lr;
            *reinterpret_cast<float2*>(g_xp + row * 128 + col) =
                make_float2(acc[m][n][0], acc[m][n][1]);
            *reinterpret_cast<float2*>(g_xp + (row + 8) * 128 + col) =
                make_float2(acc[m][n][2], acc[m][n][3]);
        }
    }
}

// ---------------------------------------------------------------------------
// CSR build: privatized-smem histogram producing per-edge final rank.
// ---------------------------------------------------------------------------
__global__ void hist_k(const int* __restrict__ dst) {
    __shared__ int sh[N_];                 // 40KB
    const int g = blockIdx.x / HB;
    const int chunk = blockIdx.x % HB;
    const int t = threadIdx.x;
    for (int b = t; b < N_; b += 512) sh[b] = 0;
    __syncthreads();

    const int base_e = g * E_ + chunk * EPB;
    for (int i = t; i < EPB; i += 512) {
        int e = base_e + i;
        g_rank[e] = atomicAdd(&sh[dst[e]], 1);
    }
    __syncthreads();

    for (int b = t; b < N_; b += 512) {
        int c = sh[b];
        sh[b] = (c > 0) ? atomicAdd(&g_deg[g * N_ + b], c) : 0;
    }
    __syncthreads();

    for (int i = t; i < EPB; i += 512) {
        int e = base_e + i;
        g_rank[e] += sh[dst[e]];
    }
}

__global__ void scan_k() {
    const int g = blockIdx.x;
    const int t = threadIdx.x;           // 0..1023
    __shared__ int sm[1024];
    const int base = g * N_;
    int loc[10];
    int s = 0;
    if (t < 1000) {
        #pragma unroll
        for (int i = 0; i < 10; i++) {
            loc[i] = g_deg[base + t * 10 + i];
            s += loc[i];
        }
    }
    sm[t] = s;
    __syncthreads();
    #pragma unroll
    for (int off = 1; off < 1024; off <<= 1) {
        int v = (t >= off) ? sm[t - off] : 0;
        __syncthreads();
        sm[t] += v;
        __syncthreads();
    }
    if (t < 1000) {
        int run = (t > 0 ? sm[t - 1] : 0) + g * E_;
        #pragma unroll
        for (int i = 0; i < 10; i++) {
            g_off[base + t * 10 + i] = run;
            run += loc[i];
        }
    }
}

__global__ void fill_k(const int4* __restrict__ src4,
                       const int4* __restrict__ dst4) {
    int t = blockIdx.x * blockDim.x + threadIdx.x;
    if (t >= NE_ALL / 4) return;
    int g = (t * 4) / E_;                   // E_ % 4 == 0
    int4 d = dst4[t];
    int4 s = src4[t];
    int4 r = reinterpret_cast<const int4*>(g_rank)[t];
    int b = g * N_;
    g_elist[g_off[b + d.x] + r.x] = s.x;
    g_elist[g_off[b + d.y] + r.y] = s.y;
    g_elist[g_off[b + d.z] + r.z] = s.z;
    g_elist[g_off[b + d.w] + r.w] = s.w;
}

// ---------------------------------------------------------------------------
// Gather + finalize fused: warp per node (node0..node0+ncount).
// ---------------------------------------------------------------------------
__global__ void gather_fin_k(const float* __restrict__ b_sage,
                             int node0, int ncount) {
    int ni = (int)(((long)blockIdx.x * blockDim.x + threadIdx.x) >> 5);
    int lane = threadIdx.x & 31;
    if (ni >= ncount) return;
    int node = node0 + ni;
    int g = node / N_;
    int off = g_off[node];
    int deg = g_deg[node];
    const float* xpn = g_xp + 64 + lane * 2;   // neigh half
    size_t gbase = (size_t)g * N_;

    float sx = 0.f, sy = 0.f;
    int i = 0;
    for (; i + 8 <= deg; i += 8) {
        float2 v[8];
        #pragma unroll
        for (int j = 0; j < 8; j++) {
            int s = g_elist[off + i + j];
            v[j] = *reinterpret_cast<const float2*>(xpn + (gbase + s) * 128);
        }
        #pragma unroll
        for (int j = 0; j < 8; j++) { sx += v[j].x; sy += v[j].y; }
    }
    for (; i + 4 <= deg; i += 4) {
        float2 v[4];
        #pragma unroll
        for (int j = 0; j < 4; j++) {
            int s = g_elist[off + i + j];
            v[j] = *reinterpret_cast<const float2*>(xpn + (gbase + s) * 128);
        }
        #pragma unroll
        for (int j = 0; j < 4; j++) { sx += v[j].x; sy += v[j].y; }
    }
    for (; i < deg; i++) {
        int s0 = g_elist[off + i];
        float2 v0 = *reinterpret_cast<const float2*>(xpn + (gbase + s0) * 128);
        sx += v0.x;
        sy += v0.y;
    }

    float inv = 1.f / fmaxf((float)deg, 1.f);
    float2 self = *reinterpret_cast<const float2*>(
        g_xp + (size_t)node * 128 + lane * 2);
    float2 bs = *reinterpret_cast<const float2*>(b_sage + lane * 2);
    float h0 = self.x + sx * inv + bs.x;
    float h1 = self.y + sy * inv + bs.y;
    float ss = h0 * h0 + h1 * h1;
    #pragma unroll
    for (int o = 16; o > 0; o >>= 1)
        ss += __shfl_xor_sync(0xFFFFFFFFu, ss, o);
    float sc = 1.f / fmaxf(sqrtf(ss), 1e-12f);
    float2 outv = make_float2(h0 * sc, h1 * sc);
    *reinterpret_cast<float2*>(g_acc + (size_t)node * 64 + lane * 2) = outv;
}

// ---------------------------------------------------------------------------
// Attention: warp per pair.
// ---------------------------------------------------------------------------
__device__ __forceinline__ float fsigmoid(float x) {
    float t;
    asm("tanh.approx.f32 %0, %1;" : "=f"(t) : "f"(0.5f * x));
    return fmaf(0.5f, t, 0.5f);
}

__global__ void attn_k(const int* __restrict__ idx,
                       const float* __restrict__ w_ff2,
                       const float* __restrict__ b_ff2,
                       const float* __restrict__ w_ff1,
                       const float* __restrict__ b_ff1,
                       const float* __restrict__ w_out,
                       float* __restrict__ out) {
    int p = (int)(((long)blockIdx.x * blockDim.x + threadIdx.x) >> 5);
    int lane = threadIdx.x & 31;
    if (p >= P_) return;
    const int cb = lane * 4;

    float w2[4], wo[4];
    #pragma unroll
    for (int j = 0; j < 4; j++) { w2[j] = w_ff2[cb + j]; wo[j] = w_out[cb + j]; }
    const float bf2 = *b_ff2;
    const float bf1 = *b_ff1;

    float tv[T_][4];
    #pragma unroll
    for (int t = 0; t < T_; t++) {
        int i0 = idx[t * P_ + p];
        int i1 = idx[T_ * P_ + t * P_ + p];
        const float* row = (lane < 16)
            ? g_acc + ((size_t)(t * N_ + i0)) * 64 + cb
            : g_acc + ((size_t)((T_ + t) * N_ + i1)) * 64 + (cb - 64);
        float4 v = *reinterpret_cast<const float4*>(row);
        tv[t][0] = v.x; tv[t][1] = v.y; tv[t][2] = v.z; tv[t][3] = v.w;
    }

    float u[T_];
    #pragma unroll
    for (int t = 0; t < T_; t++) {
        float s = tv[t][0] * w2[0];
        s = fmaf(tv[t][1], w2[1], s);
        s = fmaf(tv[t][2], w2[2], s);
        s = fmaf(tv[t][3], w2[3], s);
        u[t] = s;
    }
    #pragma unroll
    for (int off = 16; off > 0; off >>= 1)
        #pragma unroll
        for (int t = 0; t < T_; t++)
            u[t] += __shfl_xor_sync(0xFFFFFFFFu, u[t], off);

    float s0 = 0.f, s1 = 0.f, s2 = 0.f;
    #pragma unroll
    for (int t = 0; t < T_; t++) {
        float wf = w_ff1[t];
        float d0 = u[t] - (t > 0 ? u[t - 1] : 0.f);
        float d1 = u[t] - (t > 1 ? u[t - 2] : 0.f);
        float d2 = u[t] - (t > 2 ? u[t - 3] : 0.f);
        s0 = fmaf(fmaxf(d0 + bf2, 0.f), wf, s0);
        s1 = fmaf(fmaxf(d1 + bf2, 0.f), wf, s1);
        s2 = fmaf(fmaxf(d2 + bf2, 0.f), wf, s2);
    }
    s0 += bf1; s1 += bf1; s2 += bf1;
    float mx = fmaxf(s0, fmaxf(s1, s2));
    float e0 = __expf(s0 - mx), e1 = __expf(s1 - mx), e2 = __expf(s2 - mx);
    float inv = 1.f / (e0 + e1 + e2);
    float sw[3] = {e0 * inv, e1 * inv, e2 * inv};

    float o[T_];
    #pragma unroll
    for (int t = 0; t < T_; t++) {
        float acc = 0.f;
        #pragma unroll
        for (int j = 0; j < 4; j++) {
            float att = 0.f;
            #pragma unroll
            for (int km = 0; km < 3; km++) {
                float d = tv[t][j] - (t > km ? tv[t - km - 1][j] : 0.f);
                att = fmaf(sw[km], fsigmoid(d), att);
            }
            acc = fmaf(tv[t][j] * att, wo[j], acc);
        }
        o[t] = acc;
    }
    #pragma unroll
    for (int off = 16; off > 0; off >>= 1)
        #pragma unroll
        for (int t = 0; t < T_; t++)
            o[t] += __shfl_xor_sync(0xFFFFFFFFu, o[t], off);

    if (lane == 0) {
        #pragma unroll
        for (int t = 0; t < T_; t++)
            out[t * P_ + p] = o[t];
    }
}

// ---------------------------------------------------------------------------
extern "C" void kernel_launch(void* const* d_in, const int* in_sizes, int n_in,
                              void* d_out, int out_size) {
    const float* x       = (const float*)d_in[0];
    const int*   src     = (const int*)  d_in[1];
    const int*   dst     = (const int*)  d_in[2];
    const int*   idx     = (const int*)  d_in[3];
    const float* w_self  = (const float*)d_in[4];
    const float* w_neigh = (const float*)d_in[5];
    const float* b_sage  = (const float*)d_in[6];
    const float* w_ff2   = (const float*)d_in[7];
    const float* b_ff2   = (const float*)d_in[8];
    const float* w_ff1   = (const float*)d_in[9];
    const float* b_ff1   = (const float*)d_in[10];
    const float* w_out   = (const float*)d_in[11];
    float* out = (float*)d_out;

    static cudaStream_t s2 = nullptr;
    static cudaEvent_t evFork = nullptr, evCSR = nullptr, evG1 = nullptr,
                       evGA = nullptr;
    if (!s2) {
        cudaStreamCreate(&s2);
        cudaEventCreateWithFlags(&evFork, cudaEventDisableTiming);
        cudaEventCreateWithFlags(&evCSR, cudaEventDisableTiming);
        cudaEventCreateWithFlags(&evG1, cudaEventDisableTiming);
        cudaEventCreateWithFlags(&evGA, cudaEventDisableTiming);
        cudaFuncSetAttribute(gemm_mma, cudaFuncAttributeMaxDynamicSharedMemorySize,
                             2 * 128 * SSTR * 4);
    }

    void* degPtr = nullptr; cudaGetSymbolAddress(&degPtr, g_deg);

    // s0: B prep + deg clear, then fork CSR chain onto s2
    b_prep<<<64, 256>>>(w_self, w_neigh);
    cudaMemsetAsync(degPtr, 0, (size_t)M_ * sizeof(int));
    cudaEventRecord(evFork, 0);
    cudaStreamWaitEvent(s2, evFork, 0);

    hist_k<<<NG * HB, 512, 0, s2>>>(dst);
    scan_k<<<NG, 1024, 0, s2>>>();
    int e4blocks = (NE_ALL / 4 + 255) / 256;
    fill_k<<<e4blocks, 256, 0, s2>>>((const int4*)src, (const int4*)dst);
    cudaEventRecord(evCSR, s2);

    // s0: GEMM halves
    gemm_mma<<<TILES_A, 256, 2 * 128 * SSTR * 4>>>(x, 0);
    cudaEventRecord(evG1, 0);
    gemm_mma<<<TILES_B, 256, 2 * 128 * SSTR * 4>>>(x, TILES_A);

    // s2: gather first half (graphs 0..11) once CSR (in-order) + gemmA done
    cudaStreamWaitEvent(s2, evG1, 0);
    gather_fin_k<<<(NODES_HALF * 32 + 255) / 256, 256, 0, s2>>>(
        b_sage, 0, NODES_HALF);
    cudaEventRecord(evGA, s2);

    // s0: gather second half (graphs 12..23) after gemmB (in-order) + CSR
    cudaStreamWaitEvent(0, evCSR, 0);
    gather_fin_k<<<(NODES_HALF * 32 + 255) / 256, 256>>>(
        b_sage, NODES_HALF, NODES_HALF);

    // join: attn needs both gathers
    cudaStreamWaitEvent(0, evGA, 0);
    attn_k<<<(P_ * 32 + 255) / 256, 256>>>(idx, w_ff2, b_ff2, w_ff1, b_ff1,
                                           w_out, out);
}